// round 1
// baseline (speedup 1.0000x reference)
#include <cuda_runtime.h>

// NeRF importance sampler:
//   inputs : rays_o[N,3], rays_d[N,3], z_vals[N,64] (sorted), weights[N,64]
//   outputs: pts[N,192,3] | z_all[N,192] | z_samples[N,128]  (flat concat)
//
// One warp per ray. 8 warps (8 rays) per 256-thread block.
//  Phase 1: load z_vals, compute cdf[63] of (weights[1..62]+1e-5) via warp scan
//  Phase 2: z_mid[63]
//  Phase 3: 128 inverse-CDF samples (binary search, 4 per lane) -> z_samples
//  Phase 4: rank-merge z_vals(64) + z_samples(128) -> z_all(192) (both sorted)
//  Phase 5: coalesced writes of z_all and pts = o + d*z

#define NRAYS_S   64
#define NRAYS_NI  128
#define NRAYS_NT  192   // 64 + 128
#define WARPS_PB  8

__global__ __launch_bounds__(256, 8)
void importance_sampler_kernel(const float* __restrict__ rays_o,
                               const float* __restrict__ rays_d,
                               const float* __restrict__ z_vals,
                               const float* __restrict__ weights,
                               float* __restrict__ out_pts,    // [N,192,3]
                               float* __restrict__ out_zall,   // [N,192]
                               float* __restrict__ out_zs,     // [N,128]
                               int n_rays)
{
    __shared__ float sh_zv [WARPS_PB][NRAYS_S];        // z_vals
    __shared__ float sh_cdf[WARPS_PB][64];             // cdf[0..62]
    __shared__ float sh_mid[WARPS_PB][64];             // z_mid[0..62]
    __shared__ float sh_zs [WARPS_PB][NRAYS_NI];       // z_samples
    __shared__ float sh_all[WARPS_PB][NRAYS_NT];       // merged

    const int warp = threadIdx.x >> 5;
    const int lane = threadIdx.x & 31;
    const int ray  = blockIdx.x * WARPS_PB + warp;
    if (ray >= n_rays) return;

    float* zv  = sh_zv [warp];
    float* cdf = sh_cdf[warp];
    float* mid = sh_mid[warp];
    float* zs  = sh_zs [warp];
    float* zal = sh_all[warp];

    const float* zrow = z_vals  + (size_t)ray * NRAYS_S;
    const float* wrow = weights + (size_t)ray * NRAYS_S;

    // ---- Phase 1: load z_vals, build cdf ----------------------------------
    float zv_a = zrow[lane];
    float zv_b = zrow[lane + 32];
    zv[lane]      = zv_a;
    zv[lane + 32] = zv_b;

    // weights[..., 1:-1] -> w[j] = weights[j+1] + 1e-5, j = 0..61
    float wa = 0.f, wb = 0.f;
    if (lane < 31) {
        wa = wrow[2 * lane + 1] + 1e-5f;
        wb = wrow[2 * lane + 2] + 1e-5f;
    }
    float local = wa + wb;
    float s = local;
    #pragma unroll
    for (int off = 1; off < 32; off <<= 1) {
        float up = __shfl_up_sync(0xffffffffu, s, off);
        if (lane >= off) s += up;
    }
    const float total = __shfl_sync(0xffffffffu, s, 31);
    const float inv_total = 1.0f / total;
    const float excl = s - local;

    if (lane == 0) cdf[0] = 0.f;
    if (lane < 31) {
        cdf[2 * lane + 1] = (excl + wa) * inv_total;
        cdf[2 * lane + 2] = (excl + wa + wb) * inv_total;
    }
    __syncwarp();

    // ---- Phase 2: z_mid[k] = 0.5*(zv[k]+zv[k+1]), k = 0..62 ---------------
    mid[lane] = 0.5f * (zv_a + zv[lane + 1]);
    if (lane < 31)
        mid[lane + 32] = 0.5f * (zv_b + zv[lane + 33]);
    __syncwarp();

    // ---- Phase 3: 128 inverse-CDF samples (4 per lane) --------------------
    float* ozs = out_zs + (size_t)ray * NRAYS_NI;
    #pragma unroll
    for (int t = 0; t < 4; t++) {
        const int i = lane + 32 * t;
        const float u = (float)i * (1.0f / 127.0f);
        // searchsorted(cdf, u, side='right'): first idx with cdf[idx] > u, in [0,63]
        int lo = 0, hi = 63;
        while (lo < hi) {
            int m = (lo + hi) >> 1;
            if (cdf[m] > u) hi = m; else lo = m + 1;
        }
        const int below = max(lo - 1, 0);
        const int above = min(lo, 62);
        const float cb = cdf[below];
        const float ca = cdf[above];
        float denom = ca - cb;
        if (denom < 1e-5f) denom = 1.0f;
        const float tt = (u - cb) / denom;
        const float bb = mid[below];
        const float v  = bb + tt * (mid[above] - bb);
        zs[i]  = v;
        ozs[i] = v;                       // coalesced
    }
    __syncwarp();

    // ---- Phase 4: rank-merge (both arrays sorted, consistent tie-break) ---
    // z_vals element i -> pos = i + #{zs < zv[i]}
    #pragma unroll
    for (int t = 0; t < 2; t++) {
        const int i = lane + 32 * t;
        const float v = zv[i];
        int lo = 0, hi = NRAYS_NI;        // lower_bound in zs
        while (lo < hi) {
            int m = (lo + hi) >> 1;
            if (zs[m] < v) lo = m + 1; else hi = m;
        }
        zal[i + lo] = v;
    }
    // zs element j -> pos = j + #{zv <= zs[j]}
    #pragma unroll
    for (int t = 0; t < 4; t++) {
        const int j = lane + 32 * t;
        const float v = zs[j];
        int lo = 0, hi = NRAYS_S;         // upper_bound in zv
        while (lo < hi) {
            int m = (lo + hi) >> 1;
            if (zv[m] <= v) lo = m + 1; else hi = m;
        }
        zal[j + lo] = v;
    }
    __syncwarp();

    // ---- Phase 5: outputs --------------------------------------------------
    float* oza = out_zall + (size_t)ray * NRAYS_NT;
    #pragma unroll
    for (int t = 0; t < 6; t++)
        oza[lane + 32 * t] = zal[lane + 32 * t];

    const float ox = rays_o[3 * (size_t)ray + 0];
    const float oy = rays_o[3 * (size_t)ray + 1];
    const float oz = rays_o[3 * (size_t)ray + 2];
    const float dx = rays_d[3 * (size_t)ray + 0];
    const float dy = rays_d[3 * (size_t)ray + 1];
    const float dz = rays_d[3 * (size_t)ray + 2];

    float* opt = out_pts + (size_t)ray * (NRAYS_NT * 3);
    #pragma unroll
    for (int t = 0; t < 18; t++) {
        const int m = lane + 32 * t;           // 0..575
        const int k = m / 3;
        const int c = m - 3 * k;
        const float z = zal[k];
        const float o = (c == 0) ? ox : ((c == 1) ? oy : oz);
        const float d = (c == 0) ? dx : ((c == 1) ? dy : dz);
        opt[m] = fmaf(d, z, o);                // coalesced
    }
}

extern "C" void kernel_launch(void* const* d_in, const int* in_sizes, int n_in,
                              void* d_out, int out_size)
{
    const float* rays_o  = (const float*)d_in[0];
    const float* rays_d  = (const float*)d_in[1];
    const float* z_vals  = (const float*)d_in[2];
    const float* weights = (const float*)d_in[3];

    const int n_rays = in_sizes[0] / 3;

    float* out_pts  = (float*)d_out;
    float* out_zall = out_pts + (size_t)n_rays * (NRAYS_NT * 3);
    float* out_zs   = out_zall + (size_t)n_rays * NRAYS_NT;

    const int blocks = (n_rays + WARPS_PB - 1) / WARPS_PB;
    importance_sampler_kernel<<<blocks, 256>>>(rays_o, rays_d, z_vals, weights,
                                               out_pts, out_zall, out_zs, n_rays);
}

// round 5
// speedup vs baseline: 1.5892x; 1.5892x over previous
#include <cuda_runtime.h>

// NeRF importance sampler:
//   inputs : rays_o[N,3], rays_d[N,3], z_vals[N,64] (sorted), weights[N,64]
//   outputs: pts[N,192,3] | z_all[N,192] | z_samples[N,128]  (flat concat)
//
// One warp per ray, 8 warps/block. Shared is a 768-float scratch per warp:
//   [0,64)=zv [64,128)=cdf(64 incl. +inf sentinel) [128,192)=mid
//   [192,320)=zs [576,768)=zal ; [0,576) reused as staged pts (phase 5).
//
// Binary searches use the branchless pow2-count form
//   pos = 0; for step = n/2..1: if (a[pos+step-1] CMP v) pos += step;
// which returns the exact count when count <= n-1 and never reads past a[n-1].
// Phase 3 guarantees count<=63 via a +inf sentinel; phase 4's zv-side search
// pre-checks the count==128 case (a[n-1] < v) explicitly.

#define NS   64
#define NI   128
#define NT   192
#define WPB  8

__global__ __launch_bounds__(256)
void importance_sampler_kernel(const float* __restrict__ rays_o,
                               const float* __restrict__ rays_d,
                               const float* __restrict__ z_vals,
                               const float* __restrict__ weights,
                               float* __restrict__ out_pts,    // [N,192,3]
                               float* __restrict__ out_zall,   // [N,192]
                               float* __restrict__ out_zs,     // [N,128]
                               int n_rays)
{
    __shared__ float sbuf[WPB][768];

    const int warp = threadIdx.x >> 5;
    const int lane = threadIdx.x & 31;
    const int ray  = blockIdx.x * WPB + warp;
    if (ray >= n_rays) return;

    float* buf = sbuf[warp];
    float* zv  = buf;          // 64
    float* cdf = buf + 64;     // 64 (63 real + sentinel)
    float* mid = buf + 128;    // 63 used
    float* zs  = buf + 192;    // 128
    float* zal = buf + 576;    // 192
    float* pst = buf;          // 576, reused after phase 4

    // ---- Phase 1: load z_vals (float2) + build cdf ------------------------
    const float2 z2 = ((const float2*)(z_vals + (size_t)ray * NS))[lane];
    ((float2*)zv)[lane] = z2;

    const float2 w2 = ((const float2*)(weights + (size_t)ray * NS))[lane];
    const float wnx = __shfl_down_sync(0xffffffffu, w2.x, 1);   // wrow[2l+2]

    // w[j] = weights[j+1] + 1e-5, j = 0..61 -> lane l<=30 owns j=2l (wa), 2l+1 (wb)
    float wa = 0.f, wb = 0.f;
    if (lane < 31) {
        wa = w2.y + 1e-5f;
        wb = wnx  + 1e-5f;
    }
    const float local = wa + wb;
    float s = local;
    #pragma unroll
    for (int off = 1; off < 32; off <<= 1) {
        float up = __shfl_up_sync(0xffffffffu, s, off);
        if (lane >= off) s += up;
    }
    const float inv_total = 1.0f / __shfl_sync(0xffffffffu, s, 31);
    const float excl = s - local;

    if (lane == 0) cdf[0] = 0.f;
    if (lane < 31) {
        cdf[2 * lane + 1] = (excl + wa) * inv_total;
        cdf[2 * lane + 2] = (excl + local) * inv_total;
    } else {
        cdf[63] = 3.402823466e+38f;    // sentinel: never counted by <= u
    }

    // ---- Phase 2: z_mid[k] = 0.5*(zv[k]+zv[k+1]), k = 0..62 ---------------
    const float znx = __shfl_down_sync(0xffffffffu, z2.x, 1);   // zv[2l+2]
    mid[2 * lane] = 0.5f * (z2.x + z2.y);                       // covers mid[62] at l=31
    if (lane < 31) mid[2 * lane + 1] = 0.5f * (z2.y + znx);
    __syncwarp();

    // ---- Phase 3: 128 inverse-CDF samples (4 per lane), keep v/lo in regs -
    float vreg[4];
    int   loreg[4];
    #pragma unroll
    for (int t = 0; t < 4; t++) {
        const int i = lane + 32 * t;
        const float u = (float)i * (1.0f / 127.0f);
        // searchsorted(cdf[0..62], u, 'right') == #{cdf[k] <= u}; sentinel
        // at cdf[63] keeps the count <= 63, within the pow2 form's range.
        int lo = 0;
        #pragma unroll
        for (int step = 32; step > 0; step >>= 1)
            if (cdf[lo + step - 1] <= u) lo += step;
        // cdf[0] = 0 <= u always -> lo >= 1
        const int below = lo - 1;
        const int above = min(lo, 62);
        const float cb = cdf[below];
        float denom = cdf[above] - cb;
        if (denom < 1e-5f) denom = 1.0f;
        const float tt = (u - cb) / denom;
        const float bb = mid[below];
        const float v  = fmaf(tt, mid[above] - bb, bb);
        zs[i]    = v;
        vreg[t]  = v;
        loreg[t] = lo;
    }
    __syncwarp();

    // ---- Phase 4: rank-merge into zal (both inputs sorted) ----------------
    // zs[j] -> pos = j + #{zv <= v}. Phase-3 gives v in [mid[lo-1], mid[lo]]
    // with zv[lo-1] < mid[lo-1] and mid[lo] < zv[lo+1], so the linear
    // upper_bound starting at cnt = min(lo, NS) is exact (<=1 extra compare)
    // and bounded by 63 (v < zv[63] always).
    #pragma unroll
    for (int t = 0; t < 4; t++) {
        const int j = lane + 32 * t;
        const float v = vreg[t];
        int cnt = min(loreg[t], NS);
        while (cnt < NS && zv[cnt] <= v) cnt++;
        zal[j + cnt] = v;
    }
    // zv[i] -> pos = i + #{zs < v}. Count can be 128 (always is for i=63,
    // since every zs <= mid[62] < zv[63]); the pow2 form only reaches 127,
    // so handle the all-below case explicitly first.
    #pragma unroll
    for (int t = 0; t < 2; t++) {
        const int i = lane + 32 * t;
        const float v = zv[i];
        int pos;
        if (zs[NI - 1] < v) {
            pos = NI;
        } else {                       // count <= 127: pow2 form is exact
            pos = 0;
            #pragma unroll
            for (int step = 64; step > 0; step >>= 1)
                if (zs[pos + step - 1] < v) pos += step;
        }
        zal[i + pos] = v;
    }
    __syncwarp();

    // ---- Copy z_samples + z_all out as float4 (zs/zal still live) ---------
    {
        float4* o4 = (float4*)(out_zs + (size_t)ray * NI);     // 32 x float4
        o4[lane] = ((const float4*)zs)[lane];

        float4* a4 = (float4*)(out_zall + (size_t)ray * NT);   // 48 x float4
        a4[lane] = ((const float4*)zal)[lane];
        if (lane < 16) a4[32 + lane] = ((const float4*)zal)[32 + lane];
    }
    __syncwarp();   // everyone done reading zs before pst overwrites it

    // ---- Phase 5: stage pts into shared (no div/mod/select), copy float4 --
    const float ox = rays_o[3 * (size_t)ray + 0];
    const float oy = rays_o[3 * (size_t)ray + 1];
    const float oz = rays_o[3 * (size_t)ray + 2];
    const float dx = rays_d[3 * (size_t)ray + 0];
    const float dy = rays_d[3 * (size_t)ray + 1];
    const float dz = rays_d[3 * (size_t)ray + 2];

    #pragma unroll
    for (int t = 0; t < 6; t++) {
        const int k = lane + 32 * t;               // point index 0..191
        const float z = zal[k];
        float* p = pst + 3 * k;                    // stride-3 STS: conflict-free
        p[0] = fmaf(dx, z, ox);
        p[1] = fmaf(dy, z, oy);
        p[2] = fmaf(dz, z, oz);
    }
    __syncwarp();

    float4* o4 = (float4*)(out_pts + (size_t)ray * (NT * 3));  // 144 x float4
    const float4* s4 = (const float4*)pst;
    #pragma unroll
    for (int t = 0; t < 4; t++)
        o4[lane + 32 * t] = s4[lane + 32 * t];
    if (lane < 16)
        o4[128 + lane] = s4[128 + lane];
}

extern "C" void kernel_launch(void* const* d_in, const int* in_sizes, int n_in,
                              void* d_out, int out_size)
{
    const float* rays_o  = (const float*)d_in[0];
    const float* rays_d  = (const float*)d_in[1];
    const float* z_vals  = (const float*)d_in[2];
    const float* weights = (const float*)d_in[3];

    const int n_rays = in_sizes[0] / 3;

    float* out_pts  = (float*)d_out;
    float* out_zall = out_pts + (size_t)n_rays * (NT * 3);
    float* out_zs   = out_zall + (size_t)n_rays * NT;

    const int blocks = (n_rays + WPB - 1) / WPB;
    importance_sampler_kernel<<<blocks, 256>>>(rays_o, rays_d, z_vals, weights,
                                               out_pts, out_zall, out_zs, n_rays);
}